// round 16
// baseline (speedup 1.0000x reference)
#include <cuda_runtime.h>
#include <cuda_bf16.h>
#include <cstdint>

#define N_ROWS 8192
#define P_COLS 8192
#define DIM    256
#define NCLS   1000

#define BM 128
#define BN 128
#define BK 32
#define KSTAGES (DIM / BK)      // 8
#define NTHREADS 128
#define GRID_MAIN ((N_ROWS / BM) * (P_COLS / BN))   // 4096
#define POS_TAIL (N_ROWS / 4)                       // 2048 blocks x 4 warps = 8192 rows

// ---------------- device scratch ----------------
__device__ __align__(16) __nv_bfloat16 d_Xh[N_ROWS * DIM];
__device__ __align__(16) __nv_bfloat16 d_Yh[P_COLS * DIM];
__device__ float d_A2m[NCLS * P_COLS];    // alpha-1 table, real-mask folded (-1e30)
__device__ float d_an_sum[N_ROWS];
__device__ float d_an_cnt[N_ROWS];
__device__ float d_ap[N_ROWS];
__device__ int   d_cstart[NCLS + 1];
__device__ int   d_posidx[P_COLS];

// ---------------- helpers ----------------
__device__ __forceinline__ uint32_t s2u(const void* p) {
    uint32_t a;
    asm("{ .reg .u64 t; cvta.to.shared.u64 t, %1; cvt.u32.u64 %0, t; }" : "=r"(a) : "l"(p));
    return a;
}
__device__ __forceinline__ void cpasync16(uint32_t s, const void* g) {
    asm volatile("cp.async.cg.shared.global [%0], [%1], 16;" :: "r"(s), "l"(g));
}
__device__ __forceinline__ void cp_commit() { asm volatile("cp.async.commit_group;"); }

__device__ __forceinline__ void ldsm4(uint32_t& r0, uint32_t& r1, uint32_t& r2, uint32_t& r3,
                                      uint32_t addr) {
    asm volatile("ldmatrix.sync.aligned.m8n8.x4.shared.b16 {%0,%1,%2,%3}, [%4];"
                 : "=r"(r0), "=r"(r1), "=r"(r2), "=r"(r3) : "r"(addr));
}
__device__ __forceinline__ void mma16816(float* d, uint32_t a0, uint32_t a1, uint32_t a2,
                                         uint32_t a3, uint32_t b0, uint32_t b1) {
    asm volatile("mma.sync.aligned.m16n8k16.row.col.f32.bf16.bf16.f32 "
                 "{%0,%1,%2,%3}, {%4,%5,%6,%7}, {%8,%9}, {%0,%1,%2,%3};"
                 : "+f"(d[0]), "+f"(d[1]), "+f"(d[2]), "+f"(d[3])
                 : "r"(a0), "r"(a1), "r"(a2), "r"(a3), "r"(b0), "r"(b1));
}

// 16B-granule swizzle for 64B rows: conflict-free cp.async stores + ldmatrix reads
__device__ __forceinline__ uint32_t sw_off(int row, int g) {
    return (uint32_t)((row * 4 + (g ^ ((row >> 1) & 3))) * 16);
}

__device__ __forceinline__ float dot8(uint4 a, uint4 b) {
    const __nv_bfloat162* pa = (const __nv_bfloat162*)&a;
    const __nv_bfloat162* pb = (const __nv_bfloat162*)&b;
    float s = 0.0f;
    #pragma unroll
    for (int i = 0; i < 4; i++) {
        float2 fa = __bfloat1622float2(pa[i]);
        float2 fb = __bfloat1622float2(pb[i]);
        s += fa.x * fb.x + fa.y * fb.y;
    }
    return s;
}

// ---------------- small kernels ----------------
// normalize + zero row accumulators (zeroing proven safe in R14)
__global__ void norm_kernel(const float* __restrict__ xe, const float* __restrict__ xp) {
    int gw   = (blockIdx.x * blockDim.x + threadIdx.x) >> 5;
    int lane = threadIdx.x & 31;
    if (gw >= N_ROWS + P_COLS) return;
    if (lane == 0 && gw < N_ROWS) { d_an_sum[gw] = 0.0f; d_an_cnt[gw] = 0.0f; }
    const float* src; __nv_bfloat16* dst;
    if (gw < N_ROWS) { src = xe + (size_t)gw * DIM;            dst = d_Xh + (size_t)gw * DIM; }
    else             { src = xp + (size_t)(gw - N_ROWS) * DIM; dst = d_Yh + (size_t)(gw - N_ROWS) * DIM; }
    float v[8]; float ss = 0.0f;
    #pragma unroll
    for (int u = 0; u < 8; u++) { v[u] = src[lane + u * 32]; ss += v[u] * v[u]; }
    #pragma unroll
    for (int o = 16; o; o >>= 1) ss += __shfl_xor_sync(0xffffffffu, ss, o);
    float inv = 1.0f / fmaxf(sqrtf(ss), 1e-8f);
    #pragma unroll
    for (int u = 0; u < 8; u++)
        dst[lane + u * 32] = __float2bfloat16(v[u] * inv);
}

__global__ void a2m_kernel(const float* __restrict__ att, const int* __restrict__ lp,
                           const int* __restrict__ reall, const int* __restrict__ isreal) {
    __shared__ float satt[NCLS];
    int c = blockIdx.x;
    for (int i = threadIdx.x; i < NCLS; i += blockDim.x) satt[i] = att[(size_t)c * NCLS + i];
    __syncthreads();
    int ir = isreal[0];
    for (int j = threadIdx.x; j < P_COLS; j += blockDim.x) {
        bool rl = ir ? (reall[j] != 0) : true;
        d_A2m[(size_t)c * P_COLS + j] = rl ? (satt[lp[j]] * 0.5f - 0.6f) : -1e30f;
    }
}

// histogram + scan + scatter (single block; zeroing moved to norm_kernel)
__global__ void posbuild_kernel(const int* __restrict__ lp, const int* __restrict__ reall,
                                const int* __restrict__ isreal) {
    __shared__ int sh[1024];
    __shared__ int shist[NCLS];
    __shared__ int scur[NCLS];
    int t = threadIdx.x;
    for (int i = t; i < NCLS; i += 1024) shist[i] = 0;
    __syncthreads();
    int ir = isreal[0];
    for (int j = t; j < P_COLS; j += 1024)
        if (!ir || reall[j]) atomicAdd(&shist[lp[j]], 1);
    __syncthreads();
    int v = (t < NCLS) ? shist[t] : 0;
    sh[t] = v;
    __syncthreads();
    for (int o = 1; o < 1024; o <<= 1) {
        int u = (t >= o) ? sh[t - o] : 0;
        __syncthreads();
        sh[t] += u;
        __syncthreads();
    }
    if (t < NCLS) { d_cstart[t] = sh[t] - v; scur[t] = sh[t] - v; }
    if (t == NCLS - 1) d_cstart[NCLS] = sh[t];
    __syncthreads();
    for (int j = t; j < P_COLS; j += 1024)
        if (!ir || reall[j]) {
            int c = lp[j];
            int o = atomicAdd(&scur[c], 1);
            d_posidx[o] = j;
        }
}

// ---------------- main: R12 GEMM core + pos tail blocks + A2m prefetch ----------------
__global__ void __launch_bounds__(NTHREADS, 2) main_kernel(const int* __restrict__ labels) {
    __shared__ __nv_bfloat16 As[3][BM * BK];   // 3 x 8 KB
    __shared__ __nv_bfloat16 Bs[3][BN * BK];   // 3 x 8 KB  (total 48 KB = static cap)

    int t = threadIdx.x;
    int wid = t >> 5, lane = t & 31;

    // --- tail blocks: positives (one warp per row); atomics commute with GEMM epilogue ---
    if (blockIdx.x >= GRID_MAIN) {
        int i = (blockIdx.x - GRID_MAIN) * 4 + wid;
        int ci = labels[i];
        uint4 xv = ((const uint4*)(d_Xh + (size_t)i * DIM))[lane];
        int s = d_cstart[ci], e = d_cstart[ci + 1];
        float ap = 0.0f, subs = 0.0f, subc = 0.0f;
        for (int p = s; p < e; p++) {
            int j = d_posidx[p];
            uint4 yv = ((const uint4*)(d_Yh + (size_t)j * DIM))[lane];
            float dot = dot8(xv, yv);
            #pragma unroll
            for (int o = 16; o; o >>= 1) dot += __shfl_xor_sync(0xffffffffu, dot, o);
            if (lane == 0) {
                float dist = 1.0f - dot;
                ap += fmaxf(dist - 0.05f, 0.0f);
                float v = d_A2m[(size_t)ci * P_COLS + j] + dot;   // alpha - dist
                if (v > 0.0f) { subs += v; subc += 1.0f; }
            }
        }
        if (lane == 0) {
            d_ap[i] = ap / ((float)(e - s) + 1e-5f);
            atomicAdd(&d_an_sum[i], -subs);
            atomicAdd(&d_an_cnt[i], -subc);
        }
        return;
    }

    int warp_m = wid >> 1, warp_n = wid & 1;     // 2 x 2 warp grid, 64x64 tiles
    int mt = blockIdx.x & 63, nt = blockIdx.x >> 6;
    int row0 = mt * BM, j0 = nt * BN;

    uint32_t asb[3] = { s2u(As[0]), s2u(As[1]), s2u(As[2]) };
    uint32_t bsb[3] = { s2u(Bs[0]), s2u(Bs[1]), s2u(Bs[2]) };

    auto load_stage = [&](int s, int buf) {
        int k0 = s * BK;
        #pragma unroll
        for (int u = 0; u < 4; u++) {
            int idx = t + u * NTHREADS;
            int row = idx >> 2, g = idx & 3;
            cpasync16(asb[buf] + sw_off(row, g), d_Xh + (size_t)(row0 + row) * DIM + k0 + g * 8);
            cpasync16(bsb[buf] + sw_off(row, g), d_Yh + (size_t)(j0 + row) * DIM + k0 + g * 8);
        }
        cp_commit();
    };

    float acc[4][8][4];
    #pragma unroll
    for (int mf = 0; mf < 4; mf++)
        #pragma unroll
        for (int nf = 0; nf < 8; nf++)
            #pragma unroll
            for (int q = 0; q < 4; q++) acc[mf][nf][q] = 0.0f;

    load_stage(0, 0);
    load_stage(1, 1);

    int a_row = warp_m * 64 + (lane & 15);
    int a_gsel = lane >> 4;
    int b_row = warp_n * 64 + (lane & 7) + ((lane >> 4) << 3);
    int b_gsel = (lane >> 3) & 1;

    #pragma unroll
    for (int s = 0; s < KSTAGES; s++) {
        int buf = s % 3;
        if (s < KSTAGES - 1) asm volatile("cp.async.wait_group 1;");
        else                 asm volatile("cp.async.wait_group 0;");
        __syncthreads();

        uint32_t a[2][4][4], b[2][4][4];
        #pragma unroll
        for (int ks = 0; ks < 2; ks++) {
            #pragma unroll
            for (int mf = 0; mf < 4; mf++) {
                int r = a_row + mf * 16;
                int g = ks * 2 + a_gsel;
                ldsm4(a[ks][mf][0], a[ks][mf][1], a[ks][mf][2], a[ks][mf][3],
                      asb[buf] + sw_off(r, g));
            }
            #pragma unroll
            for (int nf2 = 0; nf2 < 4; nf2++) {
                int r = b_row + nf2 * 16;
                int g = ks * 2 + b_gsel;
                ldsm4(b[ks][nf2][0], b[ks][nf2][1], b[ks][nf2][2], b[ks][nf2][3],
                      bsb[buf] + sw_off(r, g));
            }
        }

        if (s + 2 < KSTAGES) {
            load_stage(s + 2, (s + 2) % 3);
        } else if (s == KSTAGES - 2 && (lane & 3) == 0) {
            // L2-prefetch the epilogue's A2m lines; overlaps final MMA bursts
            #pragma unroll
            for (int mf = 0; mf < 4; mf++) {
                int r0g = row0 + warp_m * 64 + mf * 16 + (lane >> 2);
                const float* pp0 = d_A2m + (size_t)labels[r0g] * P_COLS + j0 + warp_n * 64;
                const float* pp1 = d_A2m + (size_t)labels[r0g + 8] * P_COLS + j0 + warp_n * 64;
                asm volatile("prefetch.global.L2 [%0];" :: "l"(pp0));
                asm volatile("prefetch.global.L2 [%0];" :: "l"(pp0 + 32));
                asm volatile("prefetch.global.L2 [%0];" :: "l"(pp1));
                asm volatile("prefetch.global.L2 [%0];" :: "l"(pp1 + 32));
            }
        }

        #pragma unroll
        for (int ks = 0; ks < 2; ks++)
            #pragma unroll
            for (int mf = 0; mf < 4; mf++)
                #pragma unroll
                for (int nf = 0; nf < 8; nf++)
                    mma16816(acc[mf][nf],
                             a[ks][mf][0], a[ks][mf][1], a[ks][mf][2], a[ks][mf][3],
                             b[ks][nf >> 1][(nf & 1) * 2], b[ks][nf >> 1][(nf & 1) * 2 + 1]);
    }

    // barrier-free epilogue: hinge + quad shuffle + direct global atomics
    #pragma unroll
    for (int mf = 0; mf < 4; mf++) {
        int r0g = row0 + warp_m * 64 + mf * 16 + (lane >> 2);
        int r1g = r0g + 8;
        const float* p0 = d_A2m + (size_t)labels[r0g] * P_COLS + j0;
        const float* p1 = d_A2m + (size_t)labels[r1g] * P_COLS + j0;
        float s0 = 0, c0 = 0, s1 = 0, c1 = 0;
        #pragma unroll
        for (int nf = 0; nf < 8; nf++) {
            int cl = warp_n * 64 + nf * 8 + (lane & 3) * 2;
            float2 q0 = *(const float2*)(p0 + cl);
            float2 q1 = *(const float2*)(p1 + cl);
            float v;
            v = q0.x + acc[mf][nf][0]; if (v > 0.0f) { s0 += v; c0 += 1.0f; }
            v = q0.y + acc[mf][nf][1]; if (v > 0.0f) { s0 += v; c0 += 1.0f; }
            v = q1.x + acc[mf][nf][2]; if (v > 0.0f) { s1 += v; c1 += 1.0f; }
            v = q1.y + acc[mf][nf][3]; if (v > 0.0f) { s1 += v; c1 += 1.0f; }
        }
        #pragma unroll
        for (int o = 1; o <= 2; o <<= 1) {
            s0 += __shfl_xor_sync(0xffffffffu, s0, o);
            c0 += __shfl_xor_sync(0xffffffffu, c0, o);
            s1 += __shfl_xor_sync(0xffffffffu, s1, o);
            c1 += __shfl_xor_sync(0xffffffffu, c1, o);
        }
        if ((lane & 3) == 0) {
            atomicAdd(&d_an_sum[r0g], s0); atomicAdd(&d_an_cnt[r0g], c0);
            atomicAdd(&d_an_sum[r1g], s1); atomicAdd(&d_an_cnt[r1g], c1);
        }
    }
}

__global__ void final_kernel(float* __restrict__ out) {
    __shared__ float sh[1024];
    int t = threadIdx.x;
    float acc = 0.0f;
    for (int i = t; i < N_ROWS; i += 1024)
        acc += d_ap[i] + d_an_sum[i] / (d_an_cnt[i] + 1e-5f);
    sh[t] = acc;
    __syncthreads();
    for (int o = 512; o; o >>= 1) {
        if (t < o) sh[t] += sh[t + o];
        __syncthreads();
    }
    if (t == 0) out[0] = sh[0] / (float)N_ROWS;
}

// ---------------- launch (no host CUDA APIs besides kernel launches) ----------------
extern "C" void kernel_launch(void* const* d_in, const int* in_sizes, int n_in,
                              void* d_out, int out_size) {
    const float* inst_embed   = (const float*)d_in[0];
    const int*   labels       = (const int*)d_in[1];
    const float* inst_proxy   = (const float*)d_in[2];
    const int*   labels_proxy = (const int*)d_in[3];
    const int*   real_list    = (const int*)d_in[6];
    const int*   is_real      = (const int*)d_in[7];
    const float* att          = (const float*)d_in[8];
    float* out = (float*)d_out;

    posbuild_kernel<<<1, 1024>>>(labels_proxy, real_list, is_real);
    norm_kernel<<<(N_ROWS + P_COLS) * 32 / 256, 256>>>(inst_embed, inst_proxy);
    a2m_kernel<<<NCLS, 256>>>(att, labels_proxy, real_list, is_real);
    main_kernel<<<GRID_MAIN + POS_TAIL, NTHREADS>>>(labels);
    final_kernel<<<1, 1024>>>(out);
}

// round 17
// speedup vs baseline: 1.1739x; 1.1739x over previous
#include <cuda_runtime.h>
#include <cuda_bf16.h>
#include <cstdint>

#define N_ROWS 8192
#define P_COLS 8192
#define DIM    256
#define NCLS   1000

#define BM 128
#define BN 128
#define BK 32
#define KSTAGES (DIM / BK)      // 8
#define NTHREADS 128
#define GRID_MAIN ((N_ROWS / BM) * (P_COLS / BN))   // 4096

// ---------------- device scratch ----------------
__device__ __align__(16) __nv_bfloat16 d_Xh[N_ROWS * DIM];
__device__ __align__(16) __nv_bfloat16 d_Yh[P_COLS * DIM];
__device__ float d_A2m[NCLS * P_COLS];    // alpha-1 table, real-mask folded (-1e30)
__device__ float d_an_sum[N_ROWS];
__device__ float d_an_cnt[N_ROWS];
__device__ float d_ap[N_ROWS];
__device__ int   d_cstart[NCLS + 1];
__device__ int   d_posidx[P_COLS];

// ---------------- helpers ----------------
__device__ __forceinline__ uint32_t s2u(const void* p) {
    uint32_t a;
    asm("{ .reg .u64 t; cvta.to.shared.u64 t, %1; cvt.u32.u64 %0, t; }" : "=r"(a) : "l"(p));
    return a;
}
__device__ __forceinline__ void cpasync16(uint32_t s, const void* g) {
    asm volatile("cp.async.cg.shared.global [%0], [%1], 16;" :: "r"(s), "l"(g));
}
__device__ __forceinline__ void cp_commit() { asm volatile("cp.async.commit_group;"); }

__device__ __forceinline__ void ldsm4(uint32_t& r0, uint32_t& r1, uint32_t& r2, uint32_t& r3,
                                      uint32_t addr) {
    asm volatile("ldmatrix.sync.aligned.m8n8.x4.shared.b16 {%0,%1,%2,%3}, [%4];"
                 : "=r"(r0), "=r"(r1), "=r"(r2), "=r"(r3) : "r"(addr));
}
__device__ __forceinline__ void mma16816(float* d, uint32_t a0, uint32_t a1, uint32_t a2,
                                         uint32_t a3, uint32_t b0, uint32_t b1) {
    asm volatile("mma.sync.aligned.m16n8k16.row.col.f32.bf16.bf16.f32 "
                 "{%0,%1,%2,%3}, {%4,%5,%6,%7}, {%8,%9}, {%0,%1,%2,%3};"
                 : "+f"(d[0]), "+f"(d[1]), "+f"(d[2]), "+f"(d[3])
                 : "r"(a0), "r"(a1), "r"(a2), "r"(a3), "r"(b0), "r"(b1));
}

// 16B-granule swizzle for 64B rows: conflict-free cp.async stores + ldmatrix reads
__device__ __forceinline__ uint32_t sw_off(int row, int g) {
    return (uint32_t)((row * 4 + (g ^ ((row >> 1) & 3))) * 16);
}

// ---------------- small kernels ----------------
// normalize + zero row accumulators (zeroing move proven safe in R14/R16)
__global__ void norm_kernel(const float* __restrict__ xe, const float* __restrict__ xp) {
    int gw   = (blockIdx.x * blockDim.x + threadIdx.x) >> 5;
    int lane = threadIdx.x & 31;
    if (gw >= N_ROWS + P_COLS) return;
    if (lane == 0 && gw < N_ROWS) { d_an_sum[gw] = 0.0f; d_an_cnt[gw] = 0.0f; }
    const float* src; __nv_bfloat16* dst;
    if (gw < N_ROWS) { src = xe + (size_t)gw * DIM;            dst = d_Xh + (size_t)gw * DIM; }
    else             { src = xp + (size_t)(gw - N_ROWS) * DIM; dst = d_Yh + (size_t)(gw - N_ROWS) * DIM; }
    float v[8]; float ss = 0.0f;
    #pragma unroll
    for (int u = 0; u < 8; u++) { v[u] = src[lane + u * 32]; ss += v[u] * v[u]; }
    #pragma unroll
    for (int o = 16; o; o >>= 1) ss += __shfl_xor_sync(0xffffffffu, ss, o);
    float inv = 1.0f / fmaxf(sqrtf(ss), 1e-8f);
    #pragma unroll
    for (int u = 0; u < 8; u++)
        dst[lane + u * 32] = __float2bfloat16(v[u] * inv);
}

__global__ void a2m_kernel(const float* __restrict__ att, const int* __restrict__ lp,
                           const int* __restrict__ reall, const int* __restrict__ isreal) {
    __shared__ float satt[NCLS];
    int c = blockIdx.x;
    for (int i = threadIdx.x; i < NCLS; i += blockDim.x) satt[i] = att[(size_t)c * NCLS + i];
    __syncthreads();
    int ir = isreal[0];
    for (int j = threadIdx.x; j < P_COLS; j += blockDim.x) {
        bool rl = ir ? (reall[j] != 0) : true;
        d_A2m[(size_t)c * P_COLS + j] = rl ? (satt[lp[j]] * 0.5f - 0.6f) : -1e30f;
    }
}

// histogram + scan + scatter (single block; zeroing moved to norm_kernel)
__global__ void posbuild_kernel(const int* __restrict__ lp, const int* __restrict__ reall,
                                const int* __restrict__ isreal) {
    __shared__ int sh[1024];
    __shared__ int shist[NCLS];
    __shared__ int scur[NCLS];
    int t = threadIdx.x;
    for (int i = t; i < NCLS; i += 1024) shist[i] = 0;
    __syncthreads();
    int ir = isreal[0];
    for (int j = t; j < P_COLS; j += 1024)
        if (!ir || reall[j]) atomicAdd(&shist[lp[j]], 1);
    __syncthreads();
    int v = (t < NCLS) ? shist[t] : 0;
    sh[t] = v;
    __syncthreads();
    for (int o = 1; o < 1024; o <<= 1) {
        int u = (t >= o) ? sh[t - o] : 0;
        __syncthreads();
        sh[t] += u;
        __syncthreads();
    }
    if (t < NCLS) { d_cstart[t] = sh[t] - v; scur[t] = sh[t] - v; }
    if (t == NCLS - 1) d_cstart[NCLS] = sh[t];
    __syncthreads();
    for (int j = t; j < P_COLS; j += 1024)
        if (!ir || reall[j]) {
            int c = lp[j];
            int o = atomicAdd(&scur[c], 1);
            d_posidx[o] = j;
        }
}

// ---------------- main: R12 GEMM core verbatim ----------------
__global__ void __launch_bounds__(NTHREADS, 2) main_kernel(const int* __restrict__ labels) {
    __shared__ __nv_bfloat16 As[3][BM * BK];   // 3 x 8 KB
    __shared__ __nv_bfloat16 Bs[3][BN * BK];   // 3 x 8 KB  (total 48 KB = static cap)

    int t = threadIdx.x;
    int wid = t >> 5, lane = t & 31;
    int warp_m = wid >> 1, warp_n = wid & 1;     // 2 x 2 warp grid, 64x64 tiles

    int mt = blockIdx.x & 63, nt = blockIdx.x >> 6;
    int row0 = mt * BM, j0 = nt * BN;

    uint32_t asb[3] = { s2u(As[0]), s2u(As[1]), s2u(As[2]) };
    uint32_t bsb[3] = { s2u(Bs[0]), s2u(Bs[1]), s2u(Bs[2]) };

    auto load_stage = [&](int s, int buf) {
        int k0 = s * BK;
        #pragma unroll
        for (int u = 0; u < 4; u++) {
            int idx = t + u * NTHREADS;
            int row = idx >> 2, g = idx & 3;
            cpasync16(asb[buf] + sw_off(row, g), d_Xh + (size_t)(row0 + row) * DIM + k0 + g * 8);
            cpasync16(bsb[buf] + sw_off(row, g), d_Yh + (size_t)(j0 + row) * DIM + k0 + g * 8);
        }
        cp_commit();
    };

    float acc[4][8][4];
    #pragma unroll
    for (int mf = 0; mf < 4; mf++)
        #pragma unroll
        for (int nf = 0; nf < 8; nf++)
            #pragma unroll
            for (int q = 0; q < 4; q++) acc[mf][nf][q] = 0.0f;

    load_stage(0, 0);
    load_stage(1, 1);

    int a_row = warp_m * 64 + (lane & 15);
    int a_gsel = lane >> 4;
    int b_row = warp_n * 64 + (lane & 7) + ((lane >> 4) << 3);
    int b_gsel = (lane >> 3) & 1;

    #pragma unroll
    for (int s = 0; s < KSTAGES; s++) {
        int buf = s % 3;
        if (s < KSTAGES - 1) asm volatile("cp.async.wait_group 1;");
        else                 asm volatile("cp.async.wait_group 0;");
        __syncthreads();

        uint32_t a[2][4][4], b[2][4][4];
        #pragma unroll
        for (int ks = 0; ks < 2; ks++) {
            #pragma unroll
            for (int mf = 0; mf < 4; mf++) {
                int r = a_row + mf * 16;
                int g = ks * 2 + a_gsel;
                ldsm4(a[ks][mf][0], a[ks][mf][1], a[ks][mf][2], a[ks][mf][3],
                      asb[buf] + sw_off(r, g));
            }
            #pragma unroll
            for (int nf2 = 0; nf2 < 4; nf2++) {
                int r = b_row + nf2 * 16;
                int g = ks * 2 + b_gsel;
                ldsm4(b[ks][nf2][0], b[ks][nf2][1], b[ks][nf2][2], b[ks][nf2][3],
                      bsb[buf] + sw_off(r, g));
            }
        }

        if (s + 2 < KSTAGES) load_stage(s + 2, (s + 2) % 3);

        #pragma unroll
        for (int ks = 0; ks < 2; ks++)
            #pragma unroll
            for (int mf = 0; mf < 4; mf++)
                #pragma unroll
                for (int nf = 0; nf < 8; nf++)
                    mma16816(acc[mf][nf],
                             a[ks][mf][0], a[ks][mf][1], a[ks][mf][2], a[ks][mf][3],
                             b[ks][nf >> 1][(nf & 1) * 2], b[ks][nf >> 1][(nf & 1) * 2 + 1]);
    }

    // barrier-free epilogue: hinge + quad shuffle + direct global atomics
    #pragma unroll
    for (int mf = 0; mf < 4; mf++) {
        int r0g = row0 + warp_m * 64 + mf * 16 + (lane >> 2);
        int r1g = r0g + 8;
        const float* p0 = d_A2m + (size_t)labels[r0g] * P_COLS + j0;
        const float* p1 = d_A2m + (size_t)labels[r1g] * P_COLS + j0;
        float s0 = 0, c0 = 0, s1 = 0, c1 = 0;
        #pragma unroll
        for (int nf = 0; nf < 8; nf++) {
            int cl = warp_n * 64 + nf * 8 + (lane & 3) * 2;
            float2 q0 = *(const float2*)(p0 + cl);
            float2 q1 = *(const float2*)(p1 + cl);
            float v;
            v = q0.x + acc[mf][nf][0]; if (v > 0.0f) { s0 += v; c0 += 1.0f; }
            v = q0.y + acc[mf][nf][1]; if (v > 0.0f) { s0 += v; c0 += 1.0f; }
            v = q1.x + acc[mf][nf][2]; if (v > 0.0f) { s1 += v; c1 += 1.0f; }
            v = q1.y + acc[mf][nf][3]; if (v > 0.0f) { s1 += v; c1 += 1.0f; }
        }
        #pragma unroll
        for (int o = 1; o <= 2; o <<= 1) {
            s0 += __shfl_xor_sync(0xffffffffu, s0, o);
            c0 += __shfl_xor_sync(0xffffffffu, c0, o);
            s1 += __shfl_xor_sync(0xffffffffu, s1, o);
            c1 += __shfl_xor_sync(0xffffffffu, c1, o);
        }
        if ((lane & 3) == 0) {
            atomicAdd(&d_an_sum[r0g], s0); atomicAdd(&d_an_cnt[r0g], c0);
            atomicAdd(&d_an_sum[r1g], s1); atomicAdd(&d_an_cnt[r1g], c1);
        }
    }
}

// ---------------- positives ----------------
__device__ __forceinline__ float dot8(uint4 a, uint4 b) {
    const __nv_bfloat162* pa = (const __nv_bfloat162*)&a;
    const __nv_bfloat162* pb = (const __nv_bfloat162*)&b;
    float s = 0.0f;
    #pragma unroll
    for (int i = 0; i < 4; i++) {
        float2 fa = __bfloat1622float2(pa[i]);
        float2 fb = __bfloat1622float2(pb[i]);
        s += fa.x * fb.x + fa.y * fb.y;
    }
    return s;
}

__global__ void pos_kernel(const int* __restrict__ labels) {
    int gw = (blockIdx.x * blockDim.x + threadIdx.x) >> 5;
    int lane = threadIdx.x & 31;
    if (gw >= N_ROWS) return;
    int i = gw;
    int ci = labels[i];
    uint4 xv = ((const uint4*)(d_Xh + (size_t)i * DIM))[lane];
    int s = d_cstart[ci], e = d_cstart[ci + 1];
    float ap = 0.0f, subs = 0.0f, subc = 0.0f;
    for (int p = s; p < e; p++) {
        int j = d_posidx[p];
        uint4 yv = ((const uint4*)(d_Yh + (size_t)j * DIM))[lane];
        float dot = dot8(xv, yv);
        #pragma unroll
        for (int o = 16; o; o >>= 1) dot += __shfl_xor_sync(0xffffffffu, dot, o);
        if (lane == 0) {
            float dist = 1.0f - dot;
            ap += fmaxf(dist - 0.05f, 0.0f);
            float v = d_A2m[(size_t)ci * P_COLS + j] + dot;   // alpha - dist
            if (v > 0.0f) { subs += v; subc += 1.0f; }
        }
    }
    if (lane == 0) {
        d_ap[i] = ap / ((float)(e - s) + 1e-5f);
        atomicAdd(&d_an_sum[i], -subs);
        atomicAdd(&d_an_cnt[i], -subc);
    }
}

__global__ void final_kernel(float* __restrict__ out) {
    __shared__ float sh[1024];
    int t = threadIdx.x;
    float acc = 0.0f;
    for (int i = t; i < N_ROWS; i += 1024)
        acc += d_ap[i] + d_an_sum[i] / (d_an_cnt[i] + 1e-5f);
    sh[t] = acc;
    __syncthreads();
    for (int o = 512; o; o >>= 1) {
        if (t < o) sh[t] += sh[t + o];
        __syncthreads();
    }
    if (t == 0) out[0] = sh[0] / (float)N_ROWS;
}

// ---------------- launch (no host CUDA APIs besides kernel launches) ----------------
extern "C" void kernel_launch(void* const* d_in, const int* in_sizes, int n_in,
                              void* d_out, int out_size) {
    const float* inst_embed   = (const float*)d_in[0];
    const int*   labels       = (const int*)d_in[1];
    const float* inst_proxy   = (const float*)d_in[2];
    const int*   labels_proxy = (const int*)d_in[3];
    const int*   real_list    = (const int*)d_in[6];
    const int*   is_real      = (const int*)d_in[7];
    const float* att          = (const float*)d_in[8];
    float* out = (float*)d_out;

    posbuild_kernel<<<1, 1024>>>(labels_proxy, real_list, is_real);
    norm_kernel<<<(N_ROWS + P_COLS) * 32 / 256, 256>>>(inst_embed, inst_proxy);
    a2m_kernel<<<NCLS, 256>>>(att, labels_proxy, real_list, is_real);
    main_kernel<<<GRID_MAIN, NTHREADS>>>(labels);
    pos_kernel<<<N_ROWS * 32 / 256, 256>>>(labels);
    final_kernel<<<1, 1024>>>(out);
}